// round 15
// baseline (speedup 1.0000x reference)
#include <cuda_runtime.h>
#include <cuda_fp16.h>
#include <cstdint>
#include <cstddef>

// ============================================================
// out = L1rownorm(A[8192,8192]) @ X[8192,512] @ W[512,256] + bias
//   prep_all: Xh = fp16(X), Wth = fp16(W^T)     (one merged launch)
//   Yt[256,8192](fp16) = Wth @ Xh^T             (fp16 HMMA, 256 CTAs)
//   GEMM2: 1024 equal CTAs (tile 128x64, ksplit 4) -> fp32 partials
//   reduce: out = (sum_ks P)/(sum_ks RS) + bias
// ============================================================

#define N_ROWS 8192
#define F_IN   512
#define F_OUT  256

// ---- GEMM1 (fp16): tile 64x128 ----
#define PAH 40                       // halves per smem row (80 B)
#define A_ST1 (64 * PAH * 2)         // 5120
#define B_ST1 (128 * PAH * 2)        // 10240
#define STAGE1 (A_ST1 + B_ST1)       // 15360
#define G1_SMEM (3 * STAGE1)         // 46080

// ---- GEMM2 (fp16): tile 128x64, ksplit 4 ----
#define T2_M 128
#define T2_N 64
#define CK 32
#define KSPLIT 4
#define KC_PER 64                    // 256 / KSPLIT chunks per CTA
#define A_ST  (T2_M * PAH * 2)       // 10240
#define B_ST  (T2_N * PAH * 2)       // 5120
#define B_OFF (4 * A_ST)             // 4 A stages
#define T2_SMEM (B_OFF + 8 * B_ST)   // 81920 -> 2 CTAs/SM

// merged prep grid split
#define XH_BLOCKS 2048
#define XH_HALF   (XH_BLOCKS * 256)

__device__ __align__(1024) __half g_Xh[(size_t)N_ROWS * F_IN];
__device__ __align__(1024) __half g_Wth[(size_t)F_OUT * F_IN];
__device__ __align__(1024) __half g_Yt[(size_t)F_OUT * N_ROWS];
__device__ __align__(1024) float  g_Part[(size_t)KSPLIT * N_ROWS * F_OUT];  // 32 MB
__device__ __align__(1024) float  g_RSp[(size_t)KSPLIT * N_ROWS];

// ---------------- device helpers ----------------
__device__ __forceinline__ uint32_t pack_h2(float lo, float hi) {
    uint32_t u;
    asm("cvt.rn.f16x2.f32 %0, %1, %2;" : "=r"(u) : "f"(hi), "f"(lo));
    return u;
}
__device__ __forceinline__ void mma_f16_k16(float* c, const uint32_t* a, const uint32_t* b) {
    asm volatile(
        "mma.sync.aligned.m16n8k16.row.col.f32.f16.f16.f32 "
        "{%0,%1,%2,%3}, {%4,%5,%6,%7}, {%8,%9}, {%0,%1,%2,%3};"
        : "+f"(c[0]), "+f"(c[1]), "+f"(c[2]), "+f"(c[3])
        : "r"(a[0]), "r"(a[1]), "r"(a[2]), "r"(a[3]), "r"(b[0]), "r"(b[1]));
}
__device__ __forceinline__ void cpa16(uint32_t s, const void* g) {
    asm volatile("cp.async.cg.shared.global [%0], [%1], 16;" :: "r"(s), "l"(g));
}
__device__ __forceinline__ void ldsm4(uint32_t& r0, uint32_t& r1, uint32_t& r2, uint32_t& r3,
                                      uint32_t addr) {
    asm volatile("ldmatrix.sync.aligned.m8n8.x4.shared.b16 {%0,%1,%2,%3}, [%4];"
                 : "=r"(r0), "=r"(r1), "=r"(r2), "=r"(r3) : "r"(addr));
}
__device__ __forceinline__ uint32_t smem_u32(const void* p) {
    uint32_t a;
    asm("{ .reg .u64 t; cvta.to.shared.u64 t, %1; cvt.u32.u64 %0, t; }" : "=r"(a) : "l"(p));
    return a;
}

// ---------------- merged prep: Xh = fp16(X), Wth = fp16(W^T) ----------------
__global__ void __launch_bounds__(256, 1) prep_all(
    const float* __restrict__ x, __half* __restrict__ xh,
    const float* __restrict__ w, __half* __restrict__ wth)
{
    __shared__ float t[32][33];
    const int b = blockIdx.x;
    if (b < XH_BLOCKS) {
        const int i = b * 256 + threadIdx.x;
        float4 v0 = reinterpret_cast<const float4*>(x)[i];
        float4 v1 = reinterpret_cast<const float4*>(x)[i + XH_HALF];
        uint2 o0, o1;
        o0.x = pack_h2(v0.x, v0.y); o0.y = pack_h2(v0.z, v0.w);
        o1.x = pack_h2(v1.x, v1.y); o1.y = pack_h2(v1.z, v1.w);
        reinterpret_cast<uint2*>(xh)[i] = o0;
        reinterpret_cast<uint2*>(xh)[i + XH_HALF] = o1;
    } else {
        const int bid = b - XH_BLOCKS;
        const int tx = threadIdx.x & 31;
        const int ty = threadIdx.x >> 5;
        const int fo0 = (bid & 7) * 32;
        const int fi0 = (bid >> 3) * 32;
        #pragma unroll
        for (int r = 0; r < 32; r += 8)
            t[ty + r][tx] = w[(size_t)(fi0 + ty + r) * F_OUT + fo0 + tx];
        __syncthreads();
        #pragma unroll
        for (int r = 0; r < 32; r += 8)
            wth[(size_t)(fo0 + ty + r) * F_IN + fi0 + tx] = __float2half_rn(t[tx][ty + r]);
    }
}

// ---------------- GEMM1 (fp16): Yt[256,8192] = Wth @ Xh^T, tile 64x128 ----------------
__global__ void __launch_bounds__(256, 2) gemm1_f16(
    const __half* __restrict__ P, const __half* __restrict__ Q,
    __half* __restrict__ out)
{
    extern __shared__ char smem[];
    const uint32_t sbase = smem_u32(smem);

    const int tid  = threadIdx.x;
    const int lane = tid & 31;
    const int wid  = tid >> 5;
    const int gid  = lane >> 2;
    const int tig  = lane & 3;
    const int wm   = wid >> 2;
    const int wn   = wid & 3;
    const int lrow = lane & 15;
    const int lhi  = (lane >> 4) & 1;

    const int mtile = blockIdx.x >> 6;
    const int ntile = blockIdx.x & 63;
    const int m0 = mtile * 64;
    const int n0 = ntile * 128;
    const int kchunks = F_IN / CK;

    const int rw = tid >> 2;
    const int sg = tid & 3;
    const __half* gA = P + (size_t)(m0 + rw) * F_IN + sg * 8;
    const __half* gB = Q + (size_t)(n0 + rw) * F_IN + sg * 8;

    auto issue = [&](int kc, int s) {
        uint32_t sA = sbase + s * STAGE1 + rw * 80 + sg * 16;
        uint32_t sB = sA + A_ST1;
        cpa16(sA,           gA + kc * CK);
        cpa16(sB,           gB + kc * CK);
        cpa16(sB + 64 * 80, gB + kc * CK + (size_t)64 * F_IN);
        asm volatile("cp.async.commit_group;" ::: "memory");
    };

    float acc[2][4][4];
    #pragma unroll
    for (int mi = 0; mi < 2; mi++)
        #pragma unroll
        for (int ni = 0; ni < 4; ni++)
            #pragma unroll
            for (int i = 0; i < 4; i++) acc[mi][ni][i] = 0.f;

    issue(0, 0);
    issue(1, 1);

    int s_c = 0, s_p = 2;
    for (int kc = 0; kc < kchunks; kc++) {
        asm volatile("cp.async.wait_group %0;" :: "n"(1) : "memory");
        __syncthreads();
        const uint32_t aBase = sbase + s_c * STAGE1;
        const uint32_t bBase = aBase + A_ST1;

        #pragma unroll
        for (int kh = 0; kh < 2; kh++) {
            uint32_t af[2][4], bf[4][2];
            #pragma unroll
            for (int mi = 0; mi < 2; mi++) {
                uint32_t ad = aBase + ((wm * 32 + mi * 16 + lrow) * PAH + kh * 16 + lhi * 8) * 2;
                ldsm4(af[mi][0], af[mi][1], af[mi][2], af[mi][3], ad);
            }
            #pragma unroll
            for (int np = 0; np < 2; np++) {
                uint32_t bd = bBase + ((wn * 32 + np * 16 + lrow) * PAH + kh * 16 + lhi * 8) * 2;
                uint32_t r0, r1, r2, r3;
                ldsm4(r0, r1, r2, r3, bd);
                bf[np * 2 + 0][0] = r0; bf[np * 2 + 0][1] = r2;
                bf[np * 2 + 1][0] = r1; bf[np * 2 + 1][1] = r3;
            }
            #pragma unroll
            for (int mi = 0; mi < 2; mi++)
                #pragma unroll
                for (int ni = 0; ni < 4; ni++)
                    mma_f16_k16(acc[mi][ni], af[mi], bf[ni]);
        }

        if (kc + 2 < kchunks) issue(kc + 2, s_p);
        else asm volatile("cp.async.commit_group;" ::: "memory");
        if (++s_c == 3) s_c = 0;
        if (++s_p == 3) s_p = 0;
    }

    #pragma unroll
    for (int mi = 0; mi < 2; mi++) {
        const int r0 = m0 + wm * 32 + mi * 16 + gid;
        #pragma unroll
        for (int ni = 0; ni < 4; ni++) {
            const int cg = n0 + wn * 32 + ni * 8 + tig * 2;
            *(uint32_t*)(out + (size_t)r0 * N_ROWS + cg) =
                pack_h2(acc[mi][ni][0], acc[mi][ni][1]);
            *(uint32_t*)(out + (size_t)(r0 + 8) * N_ROWS + cg) =
                pack_h2(acc[mi][ni][2], acc[mi][ni][3]);
        }
    }
}

// ---------------- GEMM2: 1024 equal CTAs -> fp32 partials ----------------
// bid = mtile*16 + ks*4 + ntile  (ntile fastest: co-start lockstep for A reuse)
__global__ void __launch_bounds__(256, 2) gemm2_f16(
    const float* __restrict__ A, const __half* __restrict__ Yt,
    float* __restrict__ P, float* __restrict__ RSp)
{
    extern __shared__ char smem[];
    const uint32_t sbase = smem_u32(smem);

    const int tid  = threadIdx.x;
    const int lane = tid & 31;
    const int wid  = tid >> 5;
    const int gid  = lane >> 2;
    const int tig  = lane & 3;
    const int wm   = wid >> 1;
    const int wn   = wid & 1;
    const int lrow = lane & 15;
    const int lhi  = (lane >> 4) & 1;

    const int bid   = blockIdx.x;
    const int mtile = bid >> 4;
    const int ks    = (bid >> 2) & 3;
    const int ntile = bid & 3;
    const int m0 = mtile * T2_M;
    const int n0 = ntile * T2_N;
    const size_t koff = (size_t)ks * (KC_PER * CK);   // element offset into K

    const int ra = tid >> 3;
    const int sa = tid & 7;
    const int rb = tid >> 2;
    const int sb = tid & 3;
    const float*  gA = A  + (size_t)(m0 + ra) * N_ROWS + koff + sa * 4;
    const __half* gB = Yt + (size_t)(n0 + rb) * N_ROWS + koff + sb * 8;

    float acc[2][4][4];
    #pragma unroll
    for (int mi = 0; mi < 2; mi++)
        #pragma unroll
        for (int ni = 0; ni < 4; ni++)
            #pragma unroll
            for (int i = 0; i < 4; i++) acc[mi][ni][i] = 0.f;
    float rsum[4] = {0.f, 0.f, 0.f, 0.f};

    auto issueB = [&](int kc) {
        if (kc < KC_PER) {
            cpa16(sbase + B_OFF + (kc & 7) * B_ST + rb * (PAH * 2) + sb * 16,
                  gB + (size_t)kc * CK);
            cpa16(sbase + B_OFF + ((kc + 1) & 7) * B_ST + rb * (PAH * 2) + sb * 16,
                  gB + (size_t)(kc + 1) * CK);
        }
        asm volatile("cp.async.commit_group;" ::: "memory");
    };
    auto ldA = [&](int kc, float4* v) {
        #pragma unroll
        for (int i = 0; i < 4; i++)
            v[i] = *(const float4*)(gA + (size_t)i * 32 * N_ROWS + (size_t)kc * CK);
    };
    auto stA = [&](int kc, const float4* v) {
        const uint32_t aw = sbase + (kc & 3) * A_ST + ra * (PAH * 2) + sa * 8;
        #pragma unroll
        for (int i = 0; i < 4; i++) {
            uint32_t h01 = pack_h2(v[i].x, v[i].y);
            uint32_t h23 = pack_h2(v[i].z, v[i].w);
            asm volatile("st.shared.v2.b32 [%0], {%1,%2};"
                         :: "r"(aw + i * 32 * (PAH * 2)), "r"(h01), "r"(h23));
            rsum[i] += (v[i].x + v[i].y) + (v[i].z + v[i].w);
        }
    };
    auto mmaChunk = [&](int kc) {
        const uint32_t aBase = sbase + (kc & 3) * A_ST;
        const uint32_t bBase = sbase + B_OFF + (kc & 7) * B_ST;
        #pragma unroll
        for (int kh = 0; kh < 2; kh++) {
            uint32_t af[2][4], bf[4][2];
            #pragma unroll
            for (int mi = 0; mi < 2; mi++) {
                uint32_t ad = aBase + ((wm * 32 + mi * 16 + lrow) * PAH + kh * 16 + lhi * 8) * 2;
                ldsm4(af[mi][0], af[mi][1], af[mi][2], af[mi][3], ad);
            }
            #pragma unroll
            for (int np = 0; np < 2; np++) {
                uint32_t bd = bBase + ((wn * 32 + np * 16 + lrow) * PAH + kh * 16 + lhi * 8) * 2;
                uint32_t r0, r1, r2, r3;
                ldsm4(r0, r1, r2, r3, bd);
                bf[np * 2 + 0][0] = r0; bf[np * 2 + 0][1] = r2;
                bf[np * 2 + 1][0] = r1; bf[np * 2 + 1][1] = r3;
            }
            #pragma unroll
            for (int mi = 0; mi < 2; mi++)
                #pragma unroll
                for (int ni = 0; ni < 4; ni++)
                    mma_f16_k16(acc[mi][ni], af[mi], bf[ni]);
        }
    };

    // prologue
    float4 vA0[4], vA1[4];
    ldA(0, vA0);
    ldA(1, vA1);
    issueB(0);
    issueB(2);

    for (int kc = 0; kc < KC_PER; kc += 2) {
        asm volatile("cp.async.wait_group %0;" :: "n"(1) : "memory");

        stA(kc, vA0);
        stA(kc + 1, vA1);
        int kn0 = kc + 2, kn1 = kc + 3;
        if (kn1 >= KC_PER) { kn0 = KC_PER - 2; kn1 = KC_PER - 1; }
        ldA(kn0, vA0);
        ldA(kn1, vA1);

        __syncthreads();

        issueB(kc + 4);

        mmaChunk(kc);
        mmaChunk(kc + 1);
    }

    // partial rowsum (ntile 0 only; identical across ntiles)
    #pragma unroll
    for (int i = 0; i < 4; i++) {
        rsum[i] += __shfl_down_sync(0xffffffffu, rsum[i], 4, 8);
        rsum[i] += __shfl_down_sync(0xffffffffu, rsum[i], 2, 8);
        rsum[i] += __shfl_down_sync(0xffffffffu, rsum[i], 1, 8);
    }
    if (ntile == 0 && sa == 0) {
        #pragma unroll
        for (int i = 0; i < 4; i++)
            RSp[(size_t)ks * N_ROWS + m0 + i * 32 + ra] = rsum[i];
    }

    // store raw partial tile into plane ks
    float* pout = P + (size_t)ks * N_ROWS * F_OUT;
    #pragma unroll
    for (int mi = 0; mi < 2; mi++) {
        const int r0 = m0 + wm * 32 + mi * 16 + gid;
        #pragma unroll
        for (int ni = 0; ni < 4; ni++) {
            const int cg = n0 + wn * 32 + ni * 8 + tig * 2;
            float2 v0, v1;
            v0.x = acc[mi][ni][0]; v0.y = acc[mi][ni][1];
            v1.x = acc[mi][ni][2]; v1.y = acc[mi][ni][3];
            *(float2*)(pout + (size_t)r0 * F_OUT + cg) = v0;
            *(float2*)(pout + (size_t)(r0 + 8) * F_OUT + cg) = v1;
        }
    }
}

// ---------------- reduce: out = (sum_ks P)/(sum_ks RS) + bias ----------------
__global__ void __launch_bounds__(256, 4) reduce_out(
    const float* __restrict__ P, const float* __restrict__ RSp,
    const float* __restrict__ bias, float* __restrict__ out)
{
    const int idx = blockIdx.x * 256 + threadIdx.x;   // over float4: 8192*64
    const int row = idx >> 6;
    const int col = (idx & 63) << 2;
    const int PLANE4 = N_ROWS * (F_OUT / 4);          // float4s per plane

    float rs = RSp[row] + RSp[N_ROWS + row]
             + RSp[2 * N_ROWS + row] + RSp[3 * N_ROWS + row];

    const float4* P4 = reinterpret_cast<const float4*>(P);
    float4 s0 = P4[idx];
    float4 s1 = P4[idx + PLANE4];
    float4 s2 = P4[idx + 2 * PLANE4];
    float4 s3 = P4[idx + 3 * PLANE4];

    const float inv = 1.f / fmaxf(rs, 1e-12f);
    const float4 bv = *(const float4*)(bias + col);
    float4 o;
    o.x = ((s0.x + s1.x) + (s2.x + s3.x)) * inv + bv.x;
    o.y = ((s0.y + s1.y) + (s2.y + s3.y)) * inv + bv.y;
    o.z = ((s0.z + s1.z) + (s2.z + s3.z)) * inv + bv.z;
    o.w = ((s0.w + s1.w) + (s2.w + s3.w)) * inv + bv.w;
    reinterpret_cast<float4*>(out)[idx] = o;
}

// ---------------- host ----------------
extern "C" void kernel_launch(void* const* d_in, const int* in_sizes, int n_in,
                              void* d_out, int out_size) {
    const float *A = nullptr, *X = nullptr, *W = nullptr, *Bi = nullptr;
    for (int i = 0; i < n_in; i++) {
        long s = in_sizes[i];
        if (s == (long)N_ROWS * N_ROWS)      A  = (const float*)d_in[i];
        else if (s == (long)N_ROWS * F_IN)   X  = (const float*)d_in[i];
        else if (s == (long)F_IN * F_OUT)    W  = (const float*)d_in[i];
        else if (s == (long)F_OUT)           Bi = (const float*)d_in[i];
    }

    void *xh = nullptr, *wth = nullptr, *yt = nullptr, *pt = nullptr, *rs = nullptr;
    cudaGetSymbolAddress(&xh, g_Xh);
    cudaGetSymbolAddress(&wth, g_Wth);
    cudaGetSymbolAddress(&yt, g_Yt);
    cudaGetSymbolAddress(&pt, g_Part);
    cudaGetSymbolAddress(&rs, g_RSp);

    cudaFuncSetAttribute(gemm1_f16, cudaFuncAttributeMaxDynamicSharedMemorySize, G1_SMEM);
    cudaFuncSetAttribute(gemm2_f16, cudaFuncAttributeMaxDynamicSharedMemorySize, T2_SMEM);

    // merged prep: Xh conversion + W transpose
    prep_all<<<XH_BLOCKS + 128, 256>>>(X, (__half*)xh, W, (__half*)wth);

    // GEMM1: Yt[256,8192] = Wth @ Xh^T
    gemm1_f16<<<4 * 64, 256, G1_SMEM>>>((const __half*)wth, (const __half*)xh, (__half*)yt);

    // GEMM2: 1024 equal CTAs -> fp32 partials (4 k-planes)
    gemm2_f16<<<64 * KSPLIT * 4, 256, T2_SMEM>>>(A, (const __half*)yt,
                                                 (float*)pt, (float*)rs);

    // reduce: out = (sum planes)/(sum rowsums) + bias
    reduce_out<<<(N_ROWS * F_OUT / 4) / 256, 256>>>(
        (const float*)pt, (const float*)rs, Bi, (float*)d_out);
}

// round 16
// speedup vs baseline: 1.0971x; 1.0971x over previous
#include <cuda_runtime.h>
#include <cuda_fp16.h>
#include <cstdint>
#include <cstddef>

// ============================================================
// out = L1rownorm(A[8192,8192]) @ X[8192,512] @ W[512,256] + bias
//   prep_all: Xh = fp16(X), Wth = fp16(W^T), zero flags
//   gemm_fused (512 CTAs):
//     bid 0..255   : gemm1 tile -> Yt[256,8192] fp16, publish flag
//     bid 256..511 : gemm2 tile (flag-gated B loads) -> out
// ============================================================

#define N_ROWS 8192
#define F_IN   512
#define F_OUT  256

// ---- GEMM1 (fp16): tile 64x128 ----
#define PAH 40                       // halves per smem row (80 B)
#define A_ST1 (64 * PAH * 2)         // 5120
#define B_ST1 (128 * PAH * 2)        // 10240
#define STAGE1 (A_ST1 + B_ST1)       // 15360  (3 stages = 46080)

// ---- GEMM2 (fp16): tile 128x64 ----
#define T2_M 128
#define T2_N 64
#define CK 32
#define A_ST  (T2_M * PAH * 2)       // 10240
#define B_ST  (T2_N * PAH * 2)       // 5120
#define B_OFF (4 * A_ST)             // 4 A stages
#define RS_OFF (B_OFF + 8 * B_ST)    // 8 B stages -> 81920
#define FU_SMEM (RS_OFF + 128 * 4)   // 82432 -> 2 CTAs/SM

// merged prep grid split
#define XH_BLOCKS 2048
#define XH_HALF   (XH_BLOCKS * 256)

__device__ __align__(1024) __half g_Xh[(size_t)N_ROWS * F_IN];
__device__ __align__(1024) __half g_Wth[(size_t)F_OUT * F_IN];
__device__ __align__(1024) __half g_Yt[(size_t)F_OUT * N_ROWS];
__device__ int g_Flags[256];
__device__ int g_Done;

// ---------------- device helpers ----------------
__device__ __forceinline__ uint32_t pack_h2(float lo, float hi) {
    uint32_t u;
    asm("cvt.rn.f16x2.f32 %0, %1, %2;" : "=r"(u) : "f"(hi), "f"(lo));
    return u;
}
__device__ __forceinline__ void mma_f16_k16(float* c, const uint32_t* a, const uint32_t* b) {
    asm volatile(
        "mma.sync.aligned.m16n8k16.row.col.f32.f16.f16.f32 "
        "{%0,%1,%2,%3}, {%4,%5,%6,%7}, {%8,%9}, {%0,%1,%2,%3};"
        : "+f"(c[0]), "+f"(c[1]), "+f"(c[2]), "+f"(c[3])
        : "r"(a[0]), "r"(a[1]), "r"(a[2]), "r"(a[3]), "r"(b[0]), "r"(b[1]));
}
__device__ __forceinline__ void cpa16(uint32_t s, const void* g) {
    asm volatile("cp.async.cg.shared.global [%0], [%1], 16;" :: "r"(s), "l"(g));
}
__device__ __forceinline__ void ldsm4(uint32_t& r0, uint32_t& r1, uint32_t& r2, uint32_t& r3,
                                      uint32_t addr) {
    asm volatile("ldmatrix.sync.aligned.m8n8.x4.shared.b16 {%0,%1,%2,%3}, [%4];"
                 : "=r"(r0), "=r"(r1), "=r"(r2), "=r"(r3) : "r"(addr));
}
__device__ __forceinline__ uint32_t smem_u32(const void* p) {
    uint32_t a;
    asm("{ .reg .u64 t; cvta.to.shared.u64 t, %1; cvt.u32.u64 %0, t; }" : "=r"(a) : "l"(p));
    return a;
}
__device__ __forceinline__ int ld_acq(const int* p) {
    int v;
    asm volatile("ld.acquire.gpu.b32 %0, [%1];" : "=r"(v) : "l"(p) : "memory");
    return v;
}

// ---------------- merged prep: Xh = fp16(X), Wth = fp16(W^T), zero flags ----------------
__global__ void __launch_bounds__(256, 1) prep_all(
    const float* __restrict__ x, __half* __restrict__ xh,
    const float* __restrict__ w, __half* __restrict__ wth)
{
    __shared__ float t[32][33];
    const int b = blockIdx.x;
    if (b < XH_BLOCKS) {
        const int i = b * 256 + threadIdx.x;
        float4 v0 = reinterpret_cast<const float4*>(x)[i];
        float4 v1 = reinterpret_cast<const float4*>(x)[i + XH_HALF];
        uint2 o0, o1;
        o0.x = pack_h2(v0.x, v0.y); o0.y = pack_h2(v0.z, v0.w);
        o1.x = pack_h2(v1.x, v1.y); o1.y = pack_h2(v1.z, v1.w);
        reinterpret_cast<uint2*>(xh)[i] = o0;
        reinterpret_cast<uint2*>(xh)[i + XH_HALF] = o1;
    } else if (b < XH_BLOCKS + 128) {
        const int bid = b - XH_BLOCKS;
        const int tx = threadIdx.x & 31;
        const int ty = threadIdx.x >> 5;
        const int fo0 = (bid & 7) * 32;
        const int fi0 = (bid >> 3) * 32;
        #pragma unroll
        for (int r = 0; r < 32; r += 8)
            t[ty + r][tx] = w[(size_t)(fi0 + ty + r) * F_OUT + fo0 + tx];
        __syncthreads();
        #pragma unroll
        for (int r = 0; r < 32; r += 8)
            wth[(size_t)(fo0 + ty + r) * F_IN + fi0 + tx] = __float2half_rn(t[tx][ty + r]);
    } else {
        // zero sync state for this run (graph replays reuse globals)
        g_Flags[threadIdx.x] = 0;
        if (threadIdx.x == 0) g_Done = 0;
    }
}

// ---------------- fused GEMM: gemm1 (bid<256) + gemm2 (bid>=256) ----------------
__global__ void __launch_bounds__(256, 2) gemm_fused(
    const __half* __restrict__ Wth, const __half* __restrict__ Xh,
    __half* __restrict__ Yt,
    const float* __restrict__ A, float* __restrict__ out,
    const float* __restrict__ bias)
{
    extern __shared__ char smem[];
    const uint32_t sbase = smem_u32(smem);
    __shared__ int s_ready;

    const int tid  = threadIdx.x;
    const int lane = tid & 31;
    const int wid  = tid >> 5;
    const int gid  = lane >> 2;
    const int tig  = lane & 3;
    const int lrow = lane & 15;
    const int lhi  = (lane >> 4) & 1;

    if (blockIdx.x < 256) {
        // ================= GEMM1 tile =================
        const int bid = blockIdx.x;
        const int wm = wid >> 2;          // 0..1
        const int wn = wid & 3;           // 0..3
        const int mtile = bid >> 6;       // 0..3
        const int ntile = bid & 63;       // 0..63
        const int m0 = mtile * 64;
        const int n0 = ntile * 128;
        const int kchunks = F_IN / CK;    // 16

        const int rw = tid >> 2;
        const int sg = tid & 3;
        const __half* gA = Wth + (size_t)(m0 + rw) * F_IN + sg * 8;
        const __half* gB = Xh  + (size_t)(n0 + rw) * F_IN + sg * 8;

        auto issue = [&](int kc, int s) {
            uint32_t sA = sbase + s * STAGE1 + rw * 80 + sg * 16;
            uint32_t sB = sA + A_ST1;
            cpa16(sA,           gA + kc * CK);
            cpa16(sB,           gB + kc * CK);
            cpa16(sB + 64 * 80, gB + kc * CK + (size_t)64 * F_IN);
            asm volatile("cp.async.commit_group;" ::: "memory");
        };

        float acc[2][4][4];
        #pragma unroll
        for (int mi = 0; mi < 2; mi++)
            #pragma unroll
            for (int ni = 0; ni < 4; ni++)
                #pragma unroll
                for (int i = 0; i < 4; i++) acc[mi][ni][i] = 0.f;

        issue(0, 0);
        issue(1, 1);

        int s_c = 0, s_p = 2;
        for (int kc = 0; kc < kchunks; kc++) {
            asm volatile("cp.async.wait_group %0;" :: "n"(1) : "memory");
            __syncthreads();
            const uint32_t aBase = sbase + s_c * STAGE1;
            const uint32_t bBase = aBase + A_ST1;

            #pragma unroll
            for (int kh = 0; kh < 2; kh++) {
                uint32_t af[2][4], bf[4][2];
                #pragma unroll
                for (int mi = 0; mi < 2; mi++) {
                    uint32_t ad = aBase + ((wm * 32 + mi * 16 + lrow) * PAH + kh * 16 + lhi * 8) * 2;
                    ldsm4(af[mi][0], af[mi][1], af[mi][2], af[mi][3], ad);
                }
                #pragma unroll
                for (int np = 0; np < 2; np++) {
                    uint32_t bd = bBase + ((wn * 32 + np * 16 + lrow) * PAH + kh * 16 + lhi * 8) * 2;
                    uint32_t r0, r1, r2, r3;
                    ldsm4(r0, r1, r2, r3, bd);
                    bf[np * 2 + 0][0] = r0; bf[np * 2 + 0][1] = r2;
                    bf[np * 2 + 1][0] = r1; bf[np * 2 + 1][1] = r3;
                }
                #pragma unroll
                for (int mi = 0; mi < 2; mi++)
                    #pragma unroll
                    for (int ni = 0; ni < 4; ni++)
                        mma_f16_k16(acc[mi][ni], af[mi], bf[ni]);
            }

            if (kc + 2 < kchunks) issue(kc + 2, s_p);
            else asm volatile("cp.async.commit_group;" ::: "memory");
            if (++s_c == 3) s_c = 0;
            if (++s_p == 3) s_p = 0;
        }

        #pragma unroll
        for (int mi = 0; mi < 2; mi++) {
            const int r0 = m0 + wm * 32 + mi * 16 + gid;
            #pragma unroll
            for (int ni = 0; ni < 4; ni++) {
                const int cg = n0 + wn * 32 + ni * 8 + tig * 2;
                *(uint32_t*)(Yt + (size_t)r0 * N_ROWS + cg) =
                    pack_h2(acc[mi][ni][0], acc[mi][ni][1]);
                *(uint32_t*)(Yt + (size_t)(r0 + 8) * N_ROWS + cg) =
                    pack_h2(acc[mi][ni][2], acc[mi][ni][3]);
            }
        }

        // publish: Yt tile visible at gpu scope, then flag + done counter
        __threadfence();
        __syncthreads();
        if (tid == 0) {
            atomicExch(&g_Flags[bid], 1);
            __threadfence();
            atomicAdd(&g_Done, 1);
        }
        return;
    }

    // ================= GEMM2 tile =================
    const int bid = blockIdx.x - 256;
    const int wm = wid >> 1;              // 0..3
    const int wn = wid & 1;               // 0..1
    const int mtile = bid >> 2;           // 0..63
    const int ntile = bid & 3;            // 0..3
    const int m0 = mtile * T2_M;
    const int n0 = ntile * T2_N;
    const int kchunks = N_ROWS / CK;      // 256
    const int frow = ntile * 64;          // gemm1 flag row for this ntile

    const int ra = tid >> 3;
    const int sa = tid & 7;
    const int rb = tid >> 2;
    const int sb = tid & 3;
    const float*  gA = A  + (size_t)(m0 + ra) * N_ROWS + sa * 4;
    const __half* gB = g_Yt + (size_t)(n0 + rb) * N_ROWS + sb * 8;

    float acc[2][4][4];
    #pragma unroll
    for (int mi = 0; mi < 2; mi++)
        #pragma unroll
        for (int ni = 0; ni < 4; ni++)
            #pragma unroll
            for (int i = 0; i < 4; i++) acc[mi][ni][i] = 0.f;
    float rsum[4] = {0.f, 0.f, 0.f, 0.f};

    auto issueB = [&](int kc) {
        if (kc < kchunks) {
            cpa16(sbase + B_OFF + (kc & 7) * B_ST + rb * (PAH * 2) + sb * 16,
                  gB + (size_t)kc * CK);
            cpa16(sbase + B_OFF + ((kc + 1) & 7) * B_ST + rb * (PAH * 2) + sb * 16,
                  gB + (size_t)(kc + 1) * CK);
        }
        asm volatile("cp.async.commit_group;" ::: "memory");
    };
    auto ldA = [&](int kc, float4* v) {
        #pragma unroll
        for (int i = 0; i < 4; i++)
            v[i] = *(const float4*)(gA + (size_t)i * 32 * N_ROWS + (size_t)kc * CK);
    };
    auto stA = [&](int kc, const float4* v) {
        const uint32_t aw = sbase + (kc & 3) * A_ST + ra * (PAH * 2) + sa * 8;
        #pragma unroll
        for (int i = 0; i < 4; i++) {
            uint32_t h01 = pack_h2(v[i].x, v[i].y);
            uint32_t h23 = pack_h2(v[i].z, v[i].w);
            asm volatile("st.shared.v2.b32 [%0], {%1,%2};"
                         :: "r"(aw + i * 32 * (PAH * 2)), "r"(h01), "r"(h23));
            rsum[i] += (v[i].x + v[i].y) + (v[i].z + v[i].w);
        }
    };
    auto mmaChunk = [&](int kc) {
        const uint32_t aBase = sbase + (kc & 3) * A_ST;
        const uint32_t bBase = sbase + B_OFF + (kc & 7) * B_ST;
        #pragma unroll
        for (int ks = 0; ks < 2; ks++) {
            uint32_t af[2][4], bf[4][2];
            #pragma unroll
            for (int mi = 0; mi < 2; mi++) {
                uint32_t ad = aBase + ((wm * 32 + mi * 16 + lrow) * PAH + ks * 16 + lhi * 8) * 2;
                ldsm4(af[mi][0], af[mi][1], af[mi][2], af[mi][3], ad);
            }
            #pragma unroll
            for (int np = 0; np < 2; np++) {
                uint32_t bd = bBase + ((wn * 32 + np * 16 + lrow) * PAH + ks * 16 + lhi * 8) * 2;
                uint32_t r0, r1, r2, r3;
                ldsm4(r0, r1, r2, r3, bd);
                bf[np * 2 + 0][0] = r0; bf[np * 2 + 0][1] = r2;
                bf[np * 2 + 1][0] = r1; bf[np * 2 + 1][1] = r3;
            }
            #pragma unroll
            for (int mi = 0; mi < 2; mi++)
                #pragma unroll
                for (int ni = 0; ni < 4; ni++)
                    mma_f16_k16(acc[mi][ni], af[mi], bf[ni]);
        }
    };
    // tid0 only: advance contiguous-ready counter to cover block `need`
    auto waitReady = [&](int need) {
        int r = s_ready;
        if (r > need) return;
        if (ld_acq(&g_Done) == 256) { s_ready = 64; return; }
        while (r <= need) {
            if (ld_acq(&g_Flags[frow + r]) != 0) r++;
            else if (ld_acq(&g_Done) == 256) { r = 64; break; }
        }
        s_ready = r;
    };

    // prologue
    float4 vA0[4], vA1[4];
    ldA(0, vA0);
    ldA(1, vA1);
    if (tid == 0) { s_ready = 0; waitReady(0); }
    __syncthreads();
    issueB(0);
    issueB(2);

    for (int kc = 0; kc < kchunks; kc += 2) {
        asm volatile("cp.async.wait_group %0;" :: "n"(1) : "memory");

        stA(kc, vA0);
        stA(kc + 1, vA1);
        int kn0 = kc + 2, kn1 = kc + 3;
        if (kn1 >= kchunks) { kn0 = kchunks - 2; kn1 = kchunks - 1; }
        ldA(kn0, vA0);
        ldA(kn1, vA1);

        if (tid == 0) {
            int need = (kc + 5) >> 2;
            if (need > 63) need = 63;
            waitReady(need);
        }
        __syncthreads();

        issueB(kc + 4);

        mmaChunk(kc);
        mmaChunk(kc + 1);
    }

    // rowsum reduce (8 lanes per row group)
    #pragma unroll
    for (int i = 0; i < 4; i++) {
        rsum[i] += __shfl_down_sync(0xffffffffu, rsum[i], 4, 8);
        rsum[i] += __shfl_down_sync(0xffffffffu, rsum[i], 2, 8);
        rsum[i] += __shfl_down_sync(0xffffffffu, rsum[i], 1, 8);
    }
    float* rs = (float*)(smem + RS_OFF);
    if (sa == 0) {
        #pragma unroll
        for (int i = 0; i < 4; i++)
            rs[i * 32 + ra] = 1.f / fmaxf(rsum[i], 1e-12f);
    }
    __syncthreads();

    // epilogue
    #pragma unroll
    for (int mi = 0; mi < 2; mi++) {
        const int r0 = wm * 32 + mi * 16 + gid;
        const float i0 = rs[r0];
        const float i1 = rs[r0 + 8];
        #pragma unroll
        for (int ni = 0; ni < 4; ni++) {
            const int cg = n0 + wn * 32 + ni * 8 + tig * 2;
            float2 bv = *(const float2*)(bias + cg);
            float2 v0, v1;
            v0.x = acc[mi][ni][0] * i0 + bv.x;
            v0.y = acc[mi][ni][1] * i0 + bv.y;
            v1.x = acc[mi][ni][2] * i1 + bv.x;
            v1.y = acc[mi][ni][3] * i1 + bv.y;
            *(float2*)(out + (size_t)(m0 + r0) * F_OUT + cg) = v0;
            *(float2*)(out + (size_t)(m0 + r0 + 8) * F_OUT + cg) = v1;
        }
    }
}

// ---------------- host ----------------
extern "C" void kernel_launch(void* const* d_in, const int* in_sizes, int n_in,
                              void* d_out, int out_size) {
    const float *A = nullptr, *X = nullptr, *W = nullptr, *Bi = nullptr;
    for (int i = 0; i < n_in; i++) {
        long s = in_sizes[i];
        if (s == (long)N_ROWS * N_ROWS)      A  = (const float*)d_in[i];
        else if (s == (long)N_ROWS * F_IN)   X  = (const float*)d_in[i];
        else if (s == (long)F_IN * F_OUT)    W  = (const float*)d_in[i];
        else if (s == (long)F_OUT)           Bi = (const float*)d_in[i];
    }

    void *xh = nullptr, *wth = nullptr, *yt = nullptr;
    cudaGetSymbolAddress(&xh, g_Xh);
    cudaGetSymbolAddress(&wth, g_Wth);
    cudaGetSymbolAddress(&yt, g_Yt);

    cudaFuncSetAttribute(gemm_fused, cudaFuncAttributeMaxDynamicSharedMemorySize, FU_SMEM);

    // merged prep: Xh conversion + W transpose + flag reset
    prep_all<<<XH_BLOCKS + 128 + 1, 256>>>(X, (__half*)xh, W, (__half*)wth);

    // fused GEMM1 + GEMM2 (256 + 256 CTAs, flag-pipelined)
    gemm_fused<<<512, 256, FU_SMEM>>>((const __half*)wth, (const __half*)xh,
                                      (__half*)yt, A, (float*)d_out, Bi);
}